// round 1
// baseline (speedup 1.0000x reference)
#include <cuda_runtime.h>
#include <cuda_bf16.h>

// LDDMM variational evolve, Gaussian kernel sigma=0.1.
//   p      = clamp(mom, -1, 1)
//   K_ij   = exp(-|x_i - x_j|^2 * 50)
//   dcp_i  = sum_j K_ij p_j
//   W_ij   = K_ij (p_i . p_j)
//   dmom_i = 100 * ( x_i * sum_j W_ij - sum_j W_ij x_j )
// Output: [dmom (N*3) | dcp (N*3)] float32.
//
// Pass 1: 2D grid (i-tiles x j-chunks). Each thread owns one i, accumulates
//         7 partials (dcp.xyz, wx.xyz, row) over its j-chunk in registers.
//         j-tiles staged through shared memory as float4+float2 (2 LDS / iter).
// Pass 2: reduce the SPLITJ partials per i, apply the 100*(x*row - wx) epilogue.
// Deterministic: fixed split, no float atomics.

#define TI      128    // threads per block in pass 1 = i's per block
#define JTILE   128    // j's staged per smem tile
#define SPLITJ  8      // independent j-chunks (partial accumulators)
#define MAXN    8192

// partials: [split][i][8]  (7 used, padded to 8 for alignment)
__device__ float g_part[SPLITJ * MAXN * 8];

__global__ void __launch_bounds__(TI)
lddmm_pass1(const float* __restrict__ mom,
            const float* __restrict__ cp,
            int N)
{
    __shared__ float4 sA[JTILE];  // (x.x, x.y, x.z, p.x)
    __shared__ float2 sB[JTILE];  // (p.y, p.z)

    const int i  = blockIdx.x * TI + threadIdx.x;
    const int jc = blockIdx.y;
    const int jchunk = N / SPLITJ;
    const int j0 = jc * jchunk;
    const int j1 = j0 + jchunk;

    float xix = 0.f, xiy = 0.f, xiz = 0.f;
    float pix = 0.f, piy = 0.f, piz = 0.f;
    if (i < N) {
        xix = cp[3*i+0]; xiy = cp[3*i+1]; xiz = cp[3*i+2];
        pix = fminf(fmaxf(mom[3*i+0], -1.f), 1.f);
        piy = fminf(fmaxf(mom[3*i+1], -1.f), 1.f);
        piz = fminf(fmaxf(mom[3*i+2], -1.f), 1.f);
    }

    float dcx = 0.f, dcy = 0.f, dcz = 0.f;   // sum K p_j
    float wxx = 0.f, wxy = 0.f, wxz = 0.f;   // sum W x_j
    float row = 0.f;                          // sum W

    for (int jt = j0; jt < j1; jt += JTILE) {
        __syncthreads();
        {
            int j = jt + threadIdx.x;   // TI == JTILE
            float ax = cp[3*j+0], ay = cp[3*j+1], az = cp[3*j+2];
            float bx = fminf(fmaxf(mom[3*j+0], -1.f), 1.f);
            float by = fminf(fmaxf(mom[3*j+1], -1.f), 1.f);
            float bz = fminf(fmaxf(mom[3*j+2], -1.f), 1.f);
            sA[threadIdx.x] = make_float4(ax, ay, az, bx);
            sB[threadIdx.x] = make_float2(by, bz);
        }
        __syncthreads();

        #pragma unroll 4
        for (int k = 0; k < JTILE; k++) {
            float4 a = sA[k];
            float2 b = sB[k];
            float dx = xix - a.x;
            float dy = xiy - a.y;
            float dz = xiz - a.z;
            float d2 = dx*dx + dy*dy + dz*dz;
            float K  = __expf(-50.0f * d2);
            float pd = pix*a.w + piy*b.x + piz*b.y;
            float w  = K * pd;
            row += w;
            wxx = fmaf(w, a.x, wxx);
            wxy = fmaf(w, a.y, wxy);
            wxz = fmaf(w, a.z, wxz);
            dcx = fmaf(K, a.w, dcx);
            dcy = fmaf(K, b.x, dcy);
            dcz = fmaf(K, b.y, dcz);
        }
    }

    if (i < N) {
        float* p = &g_part[(jc * MAXN + i) * 8];
        p[0] = dcx; p[1] = dcy; p[2] = dcz;
        p[3] = wxx; p[4] = wxy; p[5] = wxz;
        p[6] = row;
    }
}

__global__ void lddmm_pass2(const float* __restrict__ cp,
                            float* __restrict__ out,
                            int N)
{
    int i = blockIdx.x * blockDim.x + threadIdx.x;
    if (i >= N) return;

    float dcx = 0.f, dcy = 0.f, dcz = 0.f;
    float wxx = 0.f, wxy = 0.f, wxz = 0.f;
    float row = 0.f;
    #pragma unroll
    for (int s = 0; s < SPLITJ; s++) {
        const float* p = &g_part[(s * MAXN + i) * 8];
        dcx += p[0]; dcy += p[1]; dcz += p[2];
        wxx += p[3]; wxy += p[4]; wxz += p[5];
        row += p[6];
    }

    float xix = cp[3*i+0], xiy = cp[3*i+1], xiz = cp[3*i+2];
    // dmom = (1/sig^2) * (x * row - W@x), 1/sig^2 = 100
    out[3*i+0] = 100.0f * fmaf(xix, row, -wxx);
    out[3*i+1] = 100.0f * fmaf(xiy, row, -wxy);
    out[3*i+2] = 100.0f * fmaf(xiz, row, -wxz);
    out[3*N + 3*i+0] = dcx;
    out[3*N + 3*i+1] = dcy;
    out[3*N + 3*i+2] = dcz;
}

extern "C" void kernel_launch(void* const* d_in, const int* in_sizes, int n_in,
                              void* d_out, int out_size)
{
    const float* mom = (const float*)d_in[0];
    const float* cp  = (const float*)d_in[1];
    float* out = (float*)d_out;
    int N = in_sizes[0] / 3;   // 8192

    dim3 g1((N + TI - 1) / TI, SPLITJ);
    lddmm_pass1<<<g1, TI>>>(mom, cp, N);

    int t2 = 256;
    lddmm_pass2<<<(N + t2 - 1) / t2, t2>>>(cp, out, N);
}

// round 2
// speedup vs baseline: 1.0823x; 1.0823x over previous
#include <cuda_runtime.h>
#include <cuda_bf16.h>

// LDDMM variational evolve, Gaussian kernel sigma=0.1 (N=8192, D=3).
//   p      = clamp(mom, -1, 1)
//   K_ij   = exp(-50 |x_i - x_j|^2)     (via exp2, expanded-distance form)
//   dcp_i  = sum_j K_ij p_j
//   dmom_i = 100 * ( x_i * sum_j W_ij - sum_j W_ij x_j ),  W_ij = K_ij (p_i.p_j)
//
// Pass 1 inner loop uses sm_103a packed f32x2 FMAs:
//   - one packed dot chain computes (arg, p_i.p_j) together
//     arg = ai + cj + Xi.xj  in base-2 units; K = ex2.approx(arg)
//   - one packed multiplier (w, K) drives (wx_c, dc_c) accumulator pairs
//   9 fma-pipe instructions per pair (vs 18 scalar).
// Grid: 128 i-tiles x 8 j-splits = 1024 CTAs (~7/SM, single balanced wave).
// Pass 2 reduces the 8 partials per i and applies the epilogue. Deterministic.

#define TI      64     // threads per block pass 1 = i's per block
#define JTILE   128    // j's staged per smem tile
#define SPLITJ  8
#define MAXN    8192
#define L2E     1.4426950408889634f

typedef unsigned long long u64;

// partials: [split][i][8]  (7 used, padded to 8)
__device__ float g_part[SPLITJ * MAXN * 8];

__device__ __forceinline__ u64 pack2(float lo, float hi) {
    u64 r; asm("mov.b64 %0, {%1, %2};" : "=l"(r) : "f"(lo), "f"(hi)); return r;
}
__device__ __forceinline__ void unpack2(u64 v, float& lo, float& hi) {
    asm("mov.b64 {%0, %1}, %2;" : "=f"(lo), "=f"(hi) : "l"(v));
}
__device__ __forceinline__ u64 fma2(u64 a, u64 b, u64 c) {
    u64 d; asm("fma.rn.f32x2 %0, %1, %2, %3;" : "=l"(d) : "l"(a), "l"(b), "l"(c)); return d;
}
__device__ __forceinline__ u64 add2(u64 a, u64 b) {
    u64 d; asm("add.rn.f32x2 %0, %1, %2;" : "=l"(d) : "l"(a), "l"(b)); return d;
}
__device__ __forceinline__ float ex2a(float x) {
    float y; asm("ex2.approx.f32 %0, %1;" : "=f"(y) : "f"(x)); return y;
}
__device__ __forceinline__ float clamp1(float v) {
    return fminf(fmaxf(v, -1.f), 1.f);
}

__global__ void __launch_bounds__(TI)
lddmm_pass1(const float* __restrict__ mom,
            const float* __restrict__ cp,
            int N)
{
    // per j: qa = { (xj.x,pj.x), (xj.y,pj.y) },  qb = { (xj.z,pj.z), (cj, 0) }
    __shared__ ulonglong2 sQa[JTILE];
    __shared__ ulonglong2 sQb[JTILE];

    const int i  = blockIdx.x * TI + threadIdx.x;
    const int jc = blockIdx.y;
    const int jchunk = N / SPLITJ;
    const int j0 = jc * jchunk;

    float xix = cp[3*i+0], xiy = cp[3*i+1], xiz = cp[3*i+2];
    float pix = clamp1(mom[3*i+0]);
    float piy = clamp1(mom[3*i+1]);
    float piz = clamp1(mom[3*i+2]);

    const float c100 = 100.0f * L2E;
    const float cm50 = -50.0f * L2E;
    float sqi = fmaf(xix, xix, fmaf(xiy, xiy, xiz * xiz));
    const u64 X0  = pack2(c100 * xix, pix);
    const u64 X1  = pack2(c100 * xiy, piy);
    const u64 X2  = pack2(c100 * xiz, piz);
    const u64 aiP = pack2(cm50 * sqi, 0.0f);

    u64 ax2 = 0, ay2 = 0, az2 = 0;   // (wx_c, dc_c) pairs
    float row = 0.f;

    for (int jt = j0; jt < j0 + jchunk; jt += JTILE) {
        __syncthreads();
        for (int t = threadIdx.x; t < JTILE; t += TI) {
            int j = jt + t;
            float ax = cp[3*j+0], ay = cp[3*j+1], az = cp[3*j+2];
            float bx = clamp1(mom[3*j+0]);
            float by = clamp1(mom[3*j+1]);
            float bz = clamp1(mom[3*j+2]);
            float cj = cm50 * fmaf(ax, ax, fmaf(ay, ay, az * az));
            sQa[t] = make_ulonglong2(pack2(ax, bx), pack2(ay, by));
            sQb[t] = make_ulonglong2(pack2(az, bz), pack2(cj, 0.0f));
        }
        __syncthreads();

        #pragma unroll 8
        for (int k = 0; k < JTILE; k++) {
            ulonglong2 qa = sQa[k];
            ulonglong2 qb = sQb[k];
            u64 acc = add2(qb.y, aiP);        // (ai + cj, 0)
            acc = fma2(X0, qa.x, acc);
            acc = fma2(X1, qa.y, acc);
            acc = fma2(X2, qb.x, acc);        // (arg, p_i.p_j)
            float arg, pd; unpack2(acc, arg, pd);
            float K = ex2a(arg);
            float w = K * pd;
            u64 wK = pack2(w, K);
            ax2 = fma2(wK, qa.x, ax2);        // (wx.x += w*xj.x, dc.x += K*pj.x)
            ay2 = fma2(wK, qa.y, ay2);
            az2 = fma2(wK, qb.x, az2);
            row += w;
        }
    }

    float wxx, dcx, wxy, dcy, wxz, dcz;
    unpack2(ax2, wxx, dcx);
    unpack2(ay2, wxy, dcy);
    unpack2(az2, wxz, dcz);

    float* p = &g_part[(jc * MAXN + i) * 8];
    p[0] = dcx; p[1] = dcy; p[2] = dcz;
    p[3] = wxx; p[4] = wxy; p[5] = wxz;
    p[6] = row;
}

__global__ void lddmm_pass2(const float* __restrict__ cp,
                            float* __restrict__ out,
                            int N)
{
    int i = blockIdx.x * blockDim.x + threadIdx.x;
    if (i >= N) return;

    float4 s0 = make_float4(0.f, 0.f, 0.f, 0.f);
    float4 s1 = make_float4(0.f, 0.f, 0.f, 0.f);
    #pragma unroll
    for (int s = 0; s < SPLITJ; s++) {
        const float4* p = (const float4*)&g_part[(s * MAXN + i) * 8];
        float4 a = p[0], b = p[1];
        s0.x += a.x; s0.y += a.y; s0.z += a.z; s0.w += a.w;
        s1.x += b.x; s1.y += b.y; s1.z += b.z;
    }
    // s0 = (dcx,dcy,dcz,wxx), s1 = (wxy,wxz,row,-)
    float xix = cp[3*i+0], xiy = cp[3*i+1], xiz = cp[3*i+2];
    float row = s1.z;
    out[3*i+0] = 100.0f * fmaf(xix, row, -s0.w);
    out[3*i+1] = 100.0f * fmaf(xiy, row, -s1.x);
    out[3*i+2] = 100.0f * fmaf(xiz, row, -s1.y);
    out[3*N + 3*i+0] = s0.x;
    out[3*N + 3*i+1] = s0.y;
    out[3*N + 3*i+2] = s0.z;
}

extern "C" void kernel_launch(void* const* d_in, const int* in_sizes, int n_in,
                              void* d_out, int out_size)
{
    const float* mom = (const float*)d_in[0];
    const float* cp  = (const float*)d_in[1];
    float* out = (float*)d_out;
    int N = in_sizes[0] / 3;   // 8192

    dim3 g1(N / TI, SPLITJ);   // 128 x 8 = 1024 CTAs
    lddmm_pass1<<<g1, TI>>>(mom, cp, N);

    lddmm_pass2<<<(N + 127) / 128, 128>>>(cp, out, N);
}

// round 3
// speedup vs baseline: 1.1800x; 1.0902x over previous
#include <cuda_runtime.h>
#include <cuda_bf16.h>

// LDDMM variational evolve, Gaussian kernel sigma=0.1 (N=8192, D=3).
//   p      = clamp(mom, -1, 1)
//   K_ij   = exp(-50 |x_i - x_j|^2)     (exp2, expanded-distance form)
//   dcp_i  = sum_j K_ij p_j
//   dmom_i = 100 * ( x_i * sum_j W_ij - sum_j W_ij x_j ),  W_ij = K_ij (p_i.p_j)
//
// R3: pass1 threads own TWO i's (independent dot chains per staged j -> 2x ILP,
//     half the LDS + loop overhead per pair). Packed f32x2 FMAs: one chain
//     computes (arg, p_i.p_j), multiplier (w,K) drives (wx_c, dc_c) pairs.
// Grid: 64 i-blocks x 16 j-splits = 1024 CTAs (~7/SM, single balanced wave).
// Pass 2: one thread per (i,split), shfl-reduce over 16-lane groups.

#define TI      64     // threads per block pass 1; block covers 2*TI = 128 i's
#define IPB     128    // i's per block
#define JTILE   128
#define SPLITJ  16
#define MAXN    8192
#define L2E     1.4426950408889634f

typedef unsigned long long u64;

// partials: [split][i][8]  (7 used, padded to 8)
__device__ float g_part[SPLITJ * MAXN * 8];

__device__ __forceinline__ u64 pack2(float lo, float hi) {
    u64 r; asm("mov.b64 %0, {%1, %2};" : "=l"(r) : "f"(lo), "f"(hi)); return r;
}
__device__ __forceinline__ void unpack2(u64 v, float& lo, float& hi) {
    asm("mov.b64 {%0, %1}, %2;" : "=f"(lo), "=f"(hi) : "l"(v));
}
__device__ __forceinline__ u64 fma2(u64 a, u64 b, u64 c) {
    u64 d; asm("fma.rn.f32x2 %0, %1, %2, %3;" : "=l"(d) : "l"(a), "l"(b), "l"(c)); return d;
}
__device__ __forceinline__ u64 add2(u64 a, u64 b) {
    u64 d; asm("add.rn.f32x2 %0, %1, %2;" : "=l"(d) : "l"(a), "l"(b)); return d;
}
__device__ __forceinline__ float ex2a(float x) {
    float y; asm("ex2.approx.f32 %0, %1;" : "=f"(y) : "f"(x)); return y;
}
__device__ __forceinline__ float clamp1(float v) {
    return fminf(fmaxf(v, -1.f), 1.f);
}

__global__ void __launch_bounds__(TI)
lddmm_pass1(const float* __restrict__ mom,
            const float* __restrict__ cp,
            int N)
{
    // per j: qa = { (xj.x,pj.x), (xj.y,pj.y) },  qb = { (xj.z,pj.z), (cj, 0) }
    __shared__ ulonglong2 sQa[JTILE];
    __shared__ ulonglong2 sQb[JTILE];

    const int iA = blockIdx.x * IPB + threadIdx.x;        // first i
    const int iB = iA + TI;                                // second i
    const int jc = blockIdx.y;
    const int jchunk = N / SPLITJ;
    const int j0 = jc * jchunk;

    const float c100 = 100.0f * L2E;
    const float cm50 = -50.0f * L2E;

    // --- i A ---
    float xax = cp[3*iA+0], xay = cp[3*iA+1], xaz = cp[3*iA+2];
    float pax = clamp1(mom[3*iA+0]), pay = clamp1(mom[3*iA+1]), paz = clamp1(mom[3*iA+2]);
    float sqa = fmaf(xax, xax, fmaf(xay, xay, xaz * xaz));
    const u64 XA0 = pack2(c100 * xax, pax);
    const u64 XA1 = pack2(c100 * xay, pay);
    const u64 XA2 = pack2(c100 * xaz, paz);
    const u64 aiA = pack2(cm50 * sqa, 0.0f);

    // --- i B ---
    float xbx = cp[3*iB+0], xby = cp[3*iB+1], xbz = cp[3*iB+2];
    float pbx = clamp1(mom[3*iB+0]), pby = clamp1(mom[3*iB+1]), pbz = clamp1(mom[3*iB+2]);
    float sqb = fmaf(xbx, xbx, fmaf(xby, xby, xbz * xbz));
    const u64 XB0 = pack2(c100 * xbx, pbx);
    const u64 XB1 = pack2(c100 * xby, pby);
    const u64 XB2 = pack2(c100 * xbz, pbz);
    const u64 aiB = pack2(cm50 * sqb, 0.0f);

    u64 aAx = 0, aAy = 0, aAz = 0;  float rowA = 0.f;   // (wx_c, dc_c) pairs
    u64 aBx = 0, aBy = 0, aBz = 0;  float rowB = 0.f;

    for (int jt = j0; jt < j0 + jchunk; jt += JTILE) {
        __syncthreads();
        #pragma unroll
        for (int t = threadIdx.x; t < JTILE; t += TI) {
            int j = jt + t;
            float ax = cp[3*j+0], ay = cp[3*j+1], az = cp[3*j+2];
            float bx = clamp1(mom[3*j+0]);
            float by = clamp1(mom[3*j+1]);
            float bz = clamp1(mom[3*j+2]);
            float cj = cm50 * fmaf(ax, ax, fmaf(ay, ay, az * az));
            sQa[t] = make_ulonglong2(pack2(ax, bx), pack2(ay, by));
            sQb[t] = make_ulonglong2(pack2(az, bz), pack2(cj, 0.0f));
        }
        __syncthreads();

        #pragma unroll 4
        for (int k = 0; k < JTILE; k++) {
            ulonglong2 qa = sQa[k];
            ulonglong2 qb = sQb[k];

            u64 accA = add2(qb.y, aiA);
            u64 accB = add2(qb.y, aiB);
            accA = fma2(XA0, qa.x, accA);
            accB = fma2(XB0, qa.x, accB);
            accA = fma2(XA1, qa.y, accA);
            accB = fma2(XB1, qa.y, accB);
            accA = fma2(XA2, qb.x, accA);     // (argA, pA.pj)
            accB = fma2(XB2, qb.x, accB);     // (argB, pB.pj)

            float argA, pdA; unpack2(accA, argA, pdA);
            float argB, pdB; unpack2(accB, argB, pdB);
            float KA = ex2a(argA);
            float KB = ex2a(argB);
            float wA = KA * pdA;
            float wB = KB * pdB;
            u64 wKA = pack2(wA, KA);
            u64 wKB = pack2(wB, KB);

            aAx = fma2(wKA, qa.x, aAx);
            aBx = fma2(wKB, qa.x, aBx);
            aAy = fma2(wKA, qa.y, aAy);
            aBy = fma2(wKB, qa.y, aBy);
            aAz = fma2(wKA, qb.x, aAz);
            aBz = fma2(wKB, qb.x, aBz);
            rowA += wA;
            rowB += wB;
        }
    }

    {
        float wxx, dcx, wxy, dcy, wxz, dcz;
        unpack2(aAx, wxx, dcx); unpack2(aAy, wxy, dcy); unpack2(aAz, wxz, dcz);
        float* p = &g_part[(jc * MAXN + iA) * 8];
        p[0] = dcx; p[1] = dcy; p[2] = dcz;
        p[3] = wxx; p[4] = wxy; p[5] = wxz;
        p[6] = rowA;
    }
    {
        float wxx, dcx, wxy, dcy, wxz, dcz;
        unpack2(aBx, wxx, dcx); unpack2(aBy, wxy, dcy); unpack2(aBz, wxz, dcz);
        float* p = &g_part[(jc * MAXN + iB) * 8];
        p[0] = dcx; p[1] = dcy; p[2] = dcz;
        p[3] = wxx; p[4] = wxy; p[5] = wxz;
        p[6] = rowB;
    }
}

// One thread per (i, split); reduce over the 16 splits with shfl (width 16).
__global__ void __launch_bounds__(256)
lddmm_pass2(const float* __restrict__ cp,
            float* __restrict__ out,
            int N)
{
    int t = blockIdx.x * blockDim.x + threadIdx.x;  // 0 .. N*SPLITJ-1
    int i = t >> 4;
    int s = t & 15;
    if (i >= N) return;

    const float4* p = (const float4*)&g_part[(s * MAXN + i) * 8];
    float4 a = p[0];   // dcx dcy dcz wxx
    float4 b = p[1];   // wxy wxz row -

    #pragma unroll
    for (int d = 8; d > 0; d >>= 1) {
        a.x += __shfl_down_sync(0xffffffffu, a.x, d, 16);
        a.y += __shfl_down_sync(0xffffffffu, a.y, d, 16);
        a.z += __shfl_down_sync(0xffffffffu, a.z, d, 16);
        a.w += __shfl_down_sync(0xffffffffu, a.w, d, 16);
        b.x += __shfl_down_sync(0xffffffffu, b.x, d, 16);
        b.y += __shfl_down_sync(0xffffffffu, b.y, d, 16);
        b.z += __shfl_down_sync(0xffffffffu, b.z, d, 16);
    }

    if (s == 0) {
        float xix = cp[3*i+0], xiy = cp[3*i+1], xiz = cp[3*i+2];
        float row = b.z;
        out[3*i+0] = 100.0f * fmaf(xix, row, -a.w);
        out[3*i+1] = 100.0f * fmaf(xiy, row, -b.x);
        out[3*i+2] = 100.0f * fmaf(xiz, row, -b.y);
        out[3*N + 3*i+0] = a.x;
        out[3*N + 3*i+1] = a.y;
        out[3*N + 3*i+2] = a.z;
    }
}

extern "C" void kernel_launch(void* const* d_in, const int* in_sizes, int n_in,
                              void* d_out, int out_size)
{
    const float* mom = (const float*)d_in[0];
    const float* cp  = (const float*)d_in[1];
    float* out = (float*)d_out;
    int N = in_sizes[0] / 3;   // 8192

    dim3 g1(N / IPB, SPLITJ);  // 64 x 16 = 1024 CTAs
    lddmm_pass1<<<g1, TI>>>(mom, cp, N);

    int total = N * SPLITJ;    // 131072
    lddmm_pass2<<<total / 256, 256>>>(cp, out, N);
}

// round 4
// speedup vs baseline: 1.3293x; 1.1265x over previous
#include <cuda_runtime.h>
#include <cuda_bf16.h>

// LDDMM variational evolve, Gaussian kernel sigma=0.1 (N=8192, D=3).
//   p      = clamp(mom, -1, 1)
//   K_ij   = exp(-50 |x_i - x_j|^2)     (exp2, expanded-distance form)
//   dcp_i  = sum_j K_ij p_j
//   dmom_i = 100 * ( x_i * sum_j W_ij - sum_j W_ij x_j ),  W_ij = K_ij (p_i.p_j)
//
// R4: 4 i's per thread (4 independent chains per staged j), SPLITJ=64
//     -> 2048 CTAs, ~6.9 warps/SMSP. Packed f32x2 FMA inner loop as before.
// Pass 2: one warp per i reduces 64 split-partials (2/lane + shfl).

#define TI      64     // threads per block pass 1
#define IPT     4      // i's per thread
#define IPB     (TI*IPT)   // 256 i's per block
#define JTILE   128
#define SPLITJ  64
#define MAXN    8192
#define L2E     1.4426950408889634f

typedef unsigned long long u64;

// partials: [split][i][8]  (7 used, padded to 8)
__device__ float g_part[SPLITJ * MAXN * 8];

__device__ __forceinline__ u64 pack2(float lo, float hi) {
    u64 r; asm("mov.b64 %0, {%1, %2};" : "=l"(r) : "f"(lo), "f"(hi)); return r;
}
__device__ __forceinline__ void unpack2(u64 v, float& lo, float& hi) {
    asm("mov.b64 {%0, %1}, %2;" : "=f"(lo), "=f"(hi) : "l"(v));
}
__device__ __forceinline__ u64 fma2(u64 a, u64 b, u64 c) {
    u64 d; asm("fma.rn.f32x2 %0, %1, %2, %3;" : "=l"(d) : "l"(a), "l"(b), "l"(c)); return d;
}
__device__ __forceinline__ u64 add2(u64 a, u64 b) {
    u64 d; asm("add.rn.f32x2 %0, %1, %2;" : "=l"(d) : "l"(a), "l"(b)); return d;
}
__device__ __forceinline__ float ex2a(float x) {
    float y; asm("ex2.approx.f32 %0, %1;" : "=f"(y) : "f"(x)); return y;
}
__device__ __forceinline__ float clamp1(float v) {
    return fminf(fmaxf(v, -1.f), 1.f);
}

__global__ void __launch_bounds__(TI)
lddmm_pass1(const float* __restrict__ mom,
            const float* __restrict__ cp,
            int N)
{
    // per j: qa = { (xj.x,pj.x), (xj.y,pj.y) },  qb = { (xj.z,pj.z), (cj, 0) }
    __shared__ ulonglong2 sQa[JTILE];
    __shared__ ulonglong2 sQb[JTILE];

    const int jc = blockIdx.y;
    const int jchunk = N / SPLITJ;      // 128
    const int j0 = jc * jchunk;

    const float c100 = 100.0f * L2E;
    const float cm50 = -50.0f * L2E;

    // per-i state
    u64 X0[IPT], X1[IPT], X2[IPT], AI[IPT];
    u64 acx[IPT], acy[IPT], acz[IPT];
    float row[IPT];
    int ii[IPT];

    #pragma unroll
    for (int q = 0; q < IPT; q++) {
        int i = blockIdx.x * IPB + q * TI + threadIdx.x;
        ii[q] = i;
        float xx = cp[3*i+0], xy = cp[3*i+1], xz = cp[3*i+2];
        float px = clamp1(mom[3*i+0]), py = clamp1(mom[3*i+1]), pz = clamp1(mom[3*i+2]);
        float sq = fmaf(xx, xx, fmaf(xy, xy, xz * xz));
        X0[q] = pack2(c100 * xx, px);
        X1[q] = pack2(c100 * xy, py);
        X2[q] = pack2(c100 * xz, pz);
        AI[q] = pack2(cm50 * sq, 0.0f);
        acx[q] = 0; acy[q] = 0; acz[q] = 0; row[q] = 0.f;
    }

    for (int jt = j0; jt < j0 + jchunk; jt += JTILE) {
        __syncthreads();
        #pragma unroll
        for (int t = threadIdx.x; t < JTILE; t += TI) {
            int j = jt + t;
            float ax = cp[3*j+0], ay = cp[3*j+1], az = cp[3*j+2];
            float bx = clamp1(mom[3*j+0]);
            float by = clamp1(mom[3*j+1]);
            float bz = clamp1(mom[3*j+2]);
            float cj = cm50 * fmaf(ax, ax, fmaf(ay, ay, az * az));
            sQa[t] = make_ulonglong2(pack2(ax, bx), pack2(ay, by));
            sQb[t] = make_ulonglong2(pack2(az, bz), pack2(cj, 0.0f));
        }
        __syncthreads();

        #pragma unroll 4
        for (int k = 0; k < JTILE; k++) {
            ulonglong2 qa = sQa[k];
            ulonglong2 qb = sQb[k];

            u64 acc[IPT];
            #pragma unroll
            for (int q = 0; q < IPT; q++) acc[q] = add2(qb.y, AI[q]);
            #pragma unroll
            for (int q = 0; q < IPT; q++) acc[q] = fma2(X0[q], qa.x, acc[q]);
            #pragma unroll
            for (int q = 0; q < IPT; q++) acc[q] = fma2(X1[q], qa.y, acc[q]);
            #pragma unroll
            for (int q = 0; q < IPT; q++) acc[q] = fma2(X2[q], qb.x, acc[q]);

            float K[IPT], w[IPT];
            #pragma unroll
            for (int q = 0; q < IPT; q++) {
                float arg, pd; unpack2(acc[q], arg, pd);
                K[q] = ex2a(arg);
                w[q] = K[q] * pd;
            }
            #pragma unroll
            for (int q = 0; q < IPT; q++) {
                u64 wK = pack2(w[q], K[q]);
                acx[q] = fma2(wK, qa.x, acx[q]);
                acy[q] = fma2(wK, qa.y, acy[q]);
                acz[q] = fma2(wK, qb.x, acz[q]);
                row[q] += w[q];
            }
        }
    }

    #pragma unroll
    for (int q = 0; q < IPT; q++) {
        float wxx, dcx, wxy, dcy, wxz, dcz;
        unpack2(acx[q], wxx, dcx);
        unpack2(acy[q], wxy, dcy);
        unpack2(acz[q], wxz, dcz);
        float* p = &g_part[(jc * MAXN + ii[q]) * 8];
        p[0] = dcx; p[1] = dcy; p[2] = dcz;
        p[3] = wxx; p[4] = wxy; p[5] = wxz;
        p[6] = row[q];
    }
}

// One warp per i: 2 partials per lane, full-warp shfl reduce.
__global__ void __launch_bounds__(256)
lddmm_pass2(const float* __restrict__ cp,
            float* __restrict__ out,
            int N)
{
    int warp = (blockIdx.x * blockDim.x + threadIdx.x) >> 5;   // i index
    int lane = threadIdx.x & 31;
    if (warp >= N) return;
    int i = warp;

    const float4* p0 = (const float4*)&g_part[(lane * MAXN + i) * 8];
    const float4* p1 = (const float4*)&g_part[((lane + 32) * MAXN + i) * 8];
    float4 a = p0[0], b = p0[1];
    float4 a2 = p1[0], b2 = p1[1];
    a.x += a2.x; a.y += a2.y; a.z += a2.z; a.w += a2.w;
    b.x += b2.x; b.y += b2.y; b.z += b2.z;

    #pragma unroll
    for (int d = 16; d > 0; d >>= 1) {
        a.x += __shfl_down_sync(0xffffffffu, a.x, d);
        a.y += __shfl_down_sync(0xffffffffu, a.y, d);
        a.z += __shfl_down_sync(0xffffffffu, a.z, d);
        a.w += __shfl_down_sync(0xffffffffu, a.w, d);
        b.x += __shfl_down_sync(0xffffffffu, b.x, d);
        b.y += __shfl_down_sync(0xffffffffu, b.y, d);
        b.z += __shfl_down_sync(0xffffffffu, b.z, d);
    }

    if (lane == 0) {
        float xix = cp[3*i+0], xiy = cp[3*i+1], xiz = cp[3*i+2];
        float rw = b.z;
        out[3*i+0] = 100.0f * fmaf(xix, rw, -a.w);
        out[3*i+1] = 100.0f * fmaf(xiy, rw, -b.x);
        out[3*i+2] = 100.0f * fmaf(xiz, rw, -b.y);
        out[3*N + 3*i+0] = a.x;
        out[3*N + 3*i+1] = a.y;
        out[3*N + 3*i+2] = a.z;
    }
}

extern "C" void kernel_launch(void* const* d_in, const int* in_sizes, int n_in,
                              void* d_out, int out_size)
{
    const float* mom = (const float*)d_in[0];
    const float* cp  = (const float*)d_in[1];
    float* out = (float*)d_out;
    int N = in_sizes[0] / 3;   // 8192

    dim3 g1(N / IPB, SPLITJ);  // 32 x 64 = 2048 CTAs
    lddmm_pass1<<<g1, TI>>>(mom, cp, N);

    int threads = N * 32;      // one warp per i
    lddmm_pass2<<<threads / 256, 256>>>(cp, out, N);
}

// round 5
// speedup vs baseline: 1.3413x; 1.0091x over previous
#include <cuda_runtime.h>
#include <cuda_bf16.h>

// LDDMM variational evolve, Gaussian kernel sigma=0.1 (N=8192, D=3).
//   p      = clamp(mom, -1, 1)
//   K_ij   = exp(-50 |x_i - x_j|^2)     (exp2, expanded-distance form)
//   dcp_i  = sum_j K_ij p_j
//   dmom_i = 100 * ( x_i * sum_j W_ij - sum_j W_ij x_j ),  W_ij = K_ij (p_i.p_j)
//
// R5: partials transposed to [i][split][8] so pass2 reads are coalesced
//     (R4's [split][i] layout made pass2 lanes stride 64KB apart -> 10us).
//     Pass1: 4 i's/thread, packed f32x2 chains, unroll 8, float4 epilogue.
// Grid: 32 i-blocks x 64 splits = 2048 CTAs.

#define TI      64     // threads per block pass 1
#define IPT     4      // i's per thread
#define IPB     (TI*IPT)   // 256 i's per block
#define JTILE   128
#define SPLITJ  64
#define MAXN    8192
#define L2E     1.4426950408889634f

typedef unsigned long long u64;

// partials: [i][split][8]  (7 used, padded to 8)
__device__ float g_part[MAXN * SPLITJ * 8];

__device__ __forceinline__ u64 pack2(float lo, float hi) {
    u64 r; asm("mov.b64 %0, {%1, %2};" : "=l"(r) : "f"(lo), "f"(hi)); return r;
}
__device__ __forceinline__ void unpack2(u64 v, float& lo, float& hi) {
    asm("mov.b64 {%0, %1}, %2;" : "=f"(lo), "=f"(hi) : "l"(v));
}
__device__ __forceinline__ u64 fma2(u64 a, u64 b, u64 c) {
    u64 d; asm("fma.rn.f32x2 %0, %1, %2, %3;" : "=l"(d) : "l"(a), "l"(b), "l"(c)); return d;
}
__device__ __forceinline__ u64 add2(u64 a, u64 b) {
    u64 d; asm("add.rn.f32x2 %0, %1, %2;" : "=l"(d) : "l"(a), "l"(b)); return d;
}
__device__ __forceinline__ float ex2a(float x) {
    float y; asm("ex2.approx.f32 %0, %1;" : "=f"(y) : "f"(x)); return y;
}
__device__ __forceinline__ float clamp1(float v) {
    return fminf(fmaxf(v, -1.f), 1.f);
}

__global__ void __launch_bounds__(TI)
lddmm_pass1(const float* __restrict__ mom,
            const float* __restrict__ cp,
            int N)
{
    // per j: qa = { (xj.x,pj.x), (xj.y,pj.y) },  qb = { (xj.z,pj.z), (cj, 0) }
    __shared__ ulonglong2 sQa[JTILE];
    __shared__ ulonglong2 sQb[JTILE];

    const int jc = blockIdx.y;
    const int jchunk = N / SPLITJ;      // 128
    const int j0 = jc * jchunk;

    const float c100 = 100.0f * L2E;
    const float cm50 = -50.0f * L2E;

    u64 X0[IPT], X1[IPT], X2[IPT], AI[IPT];
    u64 acx[IPT], acy[IPT], acz[IPT];
    float row[IPT];
    int ii[IPT];

    #pragma unroll
    for (int q = 0; q < IPT; q++) {
        int i = blockIdx.x * IPB + q * TI + threadIdx.x;
        ii[q] = i;
        float xx = cp[3*i+0], xy = cp[3*i+1], xz = cp[3*i+2];
        float px = clamp1(mom[3*i+0]), py = clamp1(mom[3*i+1]), pz = clamp1(mom[3*i+2]);
        float sq = fmaf(xx, xx, fmaf(xy, xy, xz * xz));
        X0[q] = pack2(c100 * xx, px);
        X1[q] = pack2(c100 * xy, py);
        X2[q] = pack2(c100 * xz, pz);
        AI[q] = pack2(cm50 * sq, 0.0f);
        acx[q] = 0; acy[q] = 0; acz[q] = 0; row[q] = 0.f;
    }

    for (int jt = j0; jt < j0 + jchunk; jt += JTILE) {
        __syncthreads();
        #pragma unroll
        for (int t = threadIdx.x; t < JTILE; t += TI) {
            int j = jt + t;
            float ax = cp[3*j+0], ay = cp[3*j+1], az = cp[3*j+2];
            float bx = clamp1(mom[3*j+0]);
            float by = clamp1(mom[3*j+1]);
            float bz = clamp1(mom[3*j+2]);
            float cj = cm50 * fmaf(ax, ax, fmaf(ay, ay, az * az));
            sQa[t] = make_ulonglong2(pack2(ax, bx), pack2(ay, by));
            sQb[t] = make_ulonglong2(pack2(az, bz), pack2(cj, 0.0f));
        }
        __syncthreads();

        #pragma unroll 8
        for (int k = 0; k < JTILE; k++) {
            ulonglong2 qa = sQa[k];
            ulonglong2 qb = sQb[k];

            u64 acc[IPT];
            #pragma unroll
            for (int q = 0; q < IPT; q++) acc[q] = add2(qb.y, AI[q]);
            #pragma unroll
            for (int q = 0; q < IPT; q++) acc[q] = fma2(X0[q], qa.x, acc[q]);
            #pragma unroll
            for (int q = 0; q < IPT; q++) acc[q] = fma2(X1[q], qa.y, acc[q]);
            #pragma unroll
            for (int q = 0; q < IPT; q++) acc[q] = fma2(X2[q], qb.x, acc[q]);

            float K[IPT], w[IPT];
            #pragma unroll
            for (int q = 0; q < IPT; q++) {
                float arg, pd; unpack2(acc[q], arg, pd);
                K[q] = ex2a(arg);
                w[q] = K[q] * pd;
            }
            #pragma unroll
            for (int q = 0; q < IPT; q++) {
                u64 wK = pack2(w[q], K[q]);
                acx[q] = fma2(wK, qa.x, acx[q]);
                acy[q] = fma2(wK, qa.y, acy[q]);
                acz[q] = fma2(wK, qb.x, acz[q]);
                row[q] += w[q];
            }
        }
    }

    #pragma unroll
    for (int q = 0; q < IPT; q++) {
        float wxx, dcx, wxy, dcy, wxz, dcz;
        unpack2(acx[q], wxx, dcx);
        unpack2(acy[q], wxy, dcy);
        unpack2(acz[q], wxz, dcz);
        float4* p = (float4*)&g_part[(ii[q] * SPLITJ + jc) * 8];
        p[0] = make_float4(dcx, dcy, dcz, wxx);
        p[1] = make_float4(wxy, wxz, row[q], 0.0f);
    }
}

// One warp per i: lane handles splits (lane, lane+32); coalesced 32B/lane.
__global__ void __launch_bounds__(256)
lddmm_pass2(const float* __restrict__ cp,
            float* __restrict__ out,
            int N)
{
    int warp = (blockIdx.x * blockDim.x + threadIdx.x) >> 5;   // i index
    int lane = threadIdx.x & 31;
    if (warp >= N) return;
    int i = warp;

    const float4* p0 = (const float4*)&g_part[(i * SPLITJ + lane) * 8];
    const float4* p1 = (const float4*)&g_part[(i * SPLITJ + lane + 32) * 8];
    float4 a = p0[0], b = p0[1];
    float4 a2 = p1[0], b2 = p1[1];
    a.x += a2.x; a.y += a2.y; a.z += a2.z; a.w += a2.w;
    b.x += b2.x; b.y += b2.y; b.z += b2.z;

    #pragma unroll
    for (int d = 16; d > 0; d >>= 1) {
        a.x += __shfl_down_sync(0xffffffffu, a.x, d);
        a.y += __shfl_down_sync(0xffffffffu, a.y, d);
        a.z += __shfl_down_sync(0xffffffffu, a.z, d);
        a.w += __shfl_down_sync(0xffffffffu, a.w, d);
        b.x += __shfl_down_sync(0xffffffffu, b.x, d);
        b.y += __shfl_down_sync(0xffffffffu, b.y, d);
        b.z += __shfl_down_sync(0xffffffffu, b.z, d);
    }

    if (lane == 0) {
        float xix = cp[3*i+0], xiy = cp[3*i+1], xiz = cp[3*i+2];
        float rw = b.z;
        out[3*i+0] = 100.0f * fmaf(xix, rw, -a.w);
        out[3*i+1] = 100.0f * fmaf(xiy, rw, -b.x);
        out[3*i+2] = 100.0f * fmaf(xiz, rw, -b.y);
        out[3*N + 3*i+0] = a.x;
        out[3*N + 3*i+1] = a.y;
        out[3*N + 3*i+2] = a.z;
    }
}

extern "C" void kernel_launch(void* const* d_in, const int* in_sizes, int n_in,
                              void* d_out, int out_size)
{
    const float* mom = (const float*)d_in[0];
    const float* cp  = (const float*)d_in[1];
    float* out = (float*)d_out;
    int N = in_sizes[0] / 3;   // 8192

    dim3 g1(N / IPB, SPLITJ);  // 32 x 64 = 2048 CTAs
    lddmm_pass1<<<g1, TI>>>(mom, cp, N);

    int threads = N * 32;      // one warp per i
    lddmm_pass2<<<threads / 256, 256>>>(cp, out, N);
}